// round 11
// baseline (speedup 1.0000x reference)
#include <cuda_runtime.h>
#include <cstdint>

#define NN 20000
#define EE 640000
#define BBATCH 2
#define HH 128
#define OO 10
#define PAD 192

// ---------------- scratch ----------------------------------------------------
__device__ int   g_fill[NN];          // degree counter / final degree
__device__ int   g_ell[NN * PAD];     // ELL adjacency (src ids)
__device__ float g_dinv[NN];
__device__ int   g_is64;
__device__ __align__(16) float g_buf0[BBATCH * NN * HH];
__device__ __align__(16) float g_buf1[BBATCH * NN * HH];
__device__ float g_bnsum1[HH], g_bnsq1[HH];   // layer-1 BN stats
__device__ float g_bnsum2[HH], g_bnsq2[HH];   // layer-2 BN stats
// W fragment packs (tf32 hi/lo): 16 k-chunks x 1024 floats (16 nt x 32 lanes x 2 regs)
__device__ __align__(16) float g_fW1hi[16384];
__device__ __align__(16) float g_fW1lo[16384];
__device__ __align__(16) float g_fW2hi[16384];
__device__ __align__(16) float g_fW2lo[16384];

// ---------------- helpers ----------------------------------------------------
__device__ __forceinline__ unsigned f2tf(float x) {
    unsigned r;
    asm("cvt.rna.tf32.f32 %0, %1;" : "=r"(r) : "f"(x));
    return r;
}

// B fragment (m16n8k8 tf32, PTX spec): lane=(n&7)*4+(k&3), reg=(k&7)>>2
__device__ __forceinline__ int fragIdx(int k, int n) {
    int kt = k >> 3, kk = k & 7;
    int t = kk & 3, r = kk >> 2;
    int nt = n >> 3, g = n & 7;
    int lane = (g << 2) | t;
    return ((kt * 16 + nt) * 32 + lane) * 2 + r;   // chunk stride 1024
}

__device__ __forceinline__ void mma_tf32(float* d, unsigned a0, unsigned a1,
                                         unsigned a2, unsigned a3,
                                         unsigned b0, unsigned b1) {
    asm volatile(
        "mma.sync.aligned.m16n8k8.row.col.f32.tf32.tf32.f32 "
        "{%0,%1,%2,%3},{%4,%5,%6,%7},{%8,%9},{%0,%1,%2,%3};\n"
        : "+f"(d[0]), "+f"(d[1]), "+f"(d[2]), "+f"(d[3])
        : "r"(a0), "r"(a1), "r"(a2), "r"(a3), "r"(b0), "r"(b1));
}

__device__ __forceinline__ int edge_at2(const void* eiv, int is64, long idx) {
    return is64 ? (int)((const long long*)eiv)[idx] : ((const int*)eiv)[idx];
}

// compute BN affine coeffs for channel c from raw stats
__device__ __forceinline__ void bn_coeff(const float* bnsum, const float* bnsq,
                                         const float* gamma, const float* beta,
                                         int c, float& sc, float& sh) {
    float cnt = (float)(BBATCH * NN);
    float mean = bnsum[c] / cnt;
    float var = bnsq[c] / cnt - mean * mean;
    float inv = rsqrtf(var + 1e-5f);
    sc = gamma[c] * inv;
    sh = beta[c] - mean * sc;
}

// ---------------- graph prep -------------------------------------------------
__global__ void k_zero(const int* __restrict__ ei32) {
    int i = blockIdx.x * blockDim.x + threadIdx.x;
    if (i < NN) g_fill[i] = 0;
    if (i < HH) {
        g_bnsum1[i] = 0.f; g_bnsq1[i] = 0.f;
        g_bnsum2[i] = 0.f; g_bnsq2[i] = 0.f;
    }
    if (blockIdx.x == 0 && threadIdx.x < 32) {
        int lane = threadIdx.x;
        int nz = (ei32[2 * lane + 1] != 0) | (ei32[2 * (lane + 32) + 1] != 0);
        unsigned m = __ballot_sync(0xffffffffu, nz);
        if (lane == 0) g_is64 = (m == 0);
    }
}

__global__ void k_fill_ell(const void* __restrict__ eiv) {
    int is64 = g_is64;
    long e0 = (long)(blockIdx.x * blockDim.x + threadIdx.x) * 4;   // grid covers EE exactly
    int s[4], d[4];
#pragma unroll
    for (int i = 0; i < 4; i++) {
        s[i] = edge_at2(eiv, is64, e0 + i);
        d[i] = edge_at2(eiv, is64, (long)EE + e0 + i);
    }
#pragma unroll
    for (int i = 0; i < 4; i++) {
        int p = atomicAdd(&g_fill[d[i]], 1);
        g_ell[d[i] * PAD + p] = s[i];
    }
}

__global__ void k_dinv() {
    int i = blockIdx.x * blockDim.x + threadIdx.x;
    if (i < NN) g_dinv[i] = rsqrtf((float)(g_fill[i] + 1));   // +1 = self loop
}

// ---------------- W1+W2 fragment pack (off critical path, fork stream) -------
__global__ void k_prepw(const float* __restrict__ W1, const float* __restrict__ W2) {
    int n = threadIdx.x;
    int blk = blockIdx.x;                 // 0..31: 0-15 W1, 16-31 W2
    const float* W = (blk < 16) ? W1 : W2;
    float* fh = (blk < 16) ? g_fW1hi : g_fW2hi;
    float* fl = (blk < 16) ? g_fW1lo : g_fW2lo;
    int k0 = (blk & 15) * 8;
    for (int k = k0; k < k0 + 8; k++) {
        float w = W[k * HH + n];
        unsigned hi = f2tf(w);
        unsigned lo = f2tf(w - __uint_as_float(hi));
        int idx = fragIdx(k, n);
        fh[idx] = __uint_as_float(hi);
        fl[idx] = __uint_as_float(lo);
    }
}

// ---------------- tensor-core GEMM: C = affine(A) @ Wfrag --------------------
// B fragments read directly from global (128KB tables, L1-resident; all warps
// read identical addresses). No smem staging, no mainloop barriers.
// ALAYOUT 0: A row = b*NN+n (external x); 1: row = n*2+b (g_buf1)
template <int ALAYOUT, int WSEL, bool AFFINE>
__global__ void __launch_bounds__(256) k_gemm_tc(const float* __restrict__ Ain,
                                                 const float* __restrict__ gamma,
                                                 const float* __restrict__ beta) {
    __shared__ float sSc[HH], sSh[HH];
    const float* A = ALAYOUT ? (const float*)g_buf1 : Ain;
    const float* fH = WSEL ? g_fW2hi : g_fW1hi;
    const float* fL = WSEL ? g_fW2lo : g_fW1lo;

    int tid = threadIdx.x, lane = tid & 31, warp = tid >> 5;
    int b = blockIdx.y;
    int rowBase = blockIdx.x * 128;
    int g = lane >> 2, t = lane & 3;
    int r0 = rowBase + warp * 16 + g;
    int r1 = r0 + 8;
    int rc0 = r0 < NN ? r0 : NN - 1;
    int rc1 = r1 < NN ? r1 : NN - 1;
    long a0b = ALAYOUT ? ((long)rc0 * 2 + b) * HH : ((long)b * NN + rc0) * HH;
    long a1b = ALAYOUT ? ((long)rc1 * 2 + b) * HH : ((long)b * NN + rc1) * HH;

    if (AFFINE && tid < HH) {
        float sc, sh;
        bn_coeff(g_bnsum1, g_bnsq1, gamma, beta, tid, sc, sh);
        sSc[tid] = sc;
        sSh[tid] = sh;
    }

    float acc[16][4];
#pragma unroll
    for (int i = 0; i < 16; i++)
#pragma unroll
        for (int j = 0; j < 4; j++) acc[i][j] = 0.f;

    // A prefetch for chunk 0
    float fa0 = __ldg(A + a0b + t);
    float fa1 = __ldg(A + a1b + t);
    float fa2 = __ldg(A + a0b + t + 4);
    float fa3 = __ldg(A + a1b + t + 4);
    if (AFFINE) __syncthreads();

    for (int c = 0; c < 16; c++) {
        float nf0, nf1, nf2, nf3;
        if (c < 15) {
            int k1 = (c + 1) * 8;
            nf0 = __ldg(A + a0b + k1 + t);
            nf1 = __ldg(A + a1b + k1 + t);
            nf2 = __ldg(A + a0b + k1 + t + 4);
            nf3 = __ldg(A + a1b + k1 + t + 4);
        }
        int k0 = c * 8;
        if (AFFINE) {
            float s0 = sSc[k0 + t], h0 = sSh[k0 + t];
            float s4 = sSc[k0 + t + 4], h4 = sSh[k0 + t + 4];
            fa0 = fa0 * s0 + h0;
            fa1 = fa1 * s0 + h0;
            fa2 = fa2 * s4 + h4;
            fa3 = fa3 * s4 + h4;
        }
        // A frag (PTX spec): a0=(r0,t) a1=(r1,t) a2=(r0,t+4) a3=(r1,t+4)
        unsigned ah0 = f2tf(fa0), ah1 = f2tf(fa1), ah2 = f2tf(fa2), ah3 = f2tf(fa3);
        unsigned al0 = f2tf(fa0 - __uint_as_float(ah0));
        unsigned al1 = f2tf(fa1 - __uint_as_float(ah1));
        unsigned al2 = f2tf(fa2 - __uint_as_float(ah2));
        unsigned al3 = f2tf(fa3 - __uint_as_float(ah3));

        const float* bhp = fH + c * 1024 + lane * 2;
        const float* blp = fL + c * 1024 + lane * 2;
#pragma unroll
        for (int nt = 0; nt < 16; nt++) {
            float2 bh = __ldg((const float2*)(bhp + nt * 64));
            float2 bl = __ldg((const float2*)(blp + nt * 64));
            unsigned bh0 = __float_as_uint(bh.x), bh1 = __float_as_uint(bh.y);
            unsigned bl0 = __float_as_uint(bl.x), bl1 = __float_as_uint(bl.y);
            mma_tf32(acc[nt], ah0, ah1, ah2, ah3, bh0, bh1);
            mma_tf32(acc[nt], al0, al1, al2, al3, bh0, bh1);
            mma_tf32(acc[nt], ah0, ah1, ah2, ah3, bl0, bl1);
        }
        if (c < 15) { fa0 = nf0; fa1 = nf1; fa2 = nf2; fa3 = nf3; }
    }

#pragma unroll
    for (int nt = 0; nt < 16; nt++) {
        int col = nt * 8 + 2 * t;
        if (r0 < NN)
            *(float2*)&g_buf0[((long)r0 * 2 + b) * HH + col] =
                make_float2(acc[nt][0], acc[nt][1]);
        if (r1 < NN)
            *(float2*)&g_buf0[((long)r1 * 2 + b) * HH + col] =
                make_float2(acc[nt][2], acc[nt][3]);
    }
}

// ---------------- aggregation + fused BN stats (per-layer buffers) -----------
template <int LAYER>
__global__ void __launch_bounds__(256) k_aggbn(const float* __restrict__ bias) {
    float* bnsum = (LAYER == 1) ? g_bnsum1 : g_bnsum2;
    float* bnsq  = (LAYER == 1) ? g_bnsq1 : g_bnsq2;
    __shared__ float ssum[HH], ssq[HH];
    int tid = threadIdx.x;
    if (tid < HH) { ssum[tid] = 0.f; ssq[tid] = 0.f; }
    __syncthreads();

    int node = (blockIdx.x * blockDim.x + tid) >> 5;   // grid*8 == NN exactly
    int lane = tid & 31;
    float din = g_dinv[node];

    const float4* h4 = (const float4*)g_buf0;
    long base = (long)node * 64;
    float4 v0 = __ldg(&h4[base + lane]);
    float4 v1 = __ldg(&h4[base + 32 + lane]);
    float4 a0, a1;
    a0.x = din * v0.x; a0.y = din * v0.y; a0.z = din * v0.z; a0.w = din * v0.w;
    a1.x = din * v1.x; a1.y = din * v1.y; a1.z = din * v1.z; a1.w = din * v1.w;

    int cnt = g_fill[node];
    const int* row = g_ell + node * PAD;

#define AGG_EDGE(S)                                                        \
    {                                                                      \
        int _s = (S);                                                      \
        float w = __ldg(&g_dinv[_s]);                                      \
        long sb = (long)_s * 64;                                           \
        float4 u0 = __ldg(&h4[sb + lane]);                                 \
        float4 u1 = __ldg(&h4[sb + 32 + lane]);                            \
        a0.x += w * u0.x; a0.y += w * u0.y;                                \
        a0.z += w * u0.z; a0.w += w * u0.w;                                \
        a1.x += w * u1.x; a1.y += w * u1.y;                                \
        a1.z += w * u1.z; a1.w += w * u1.w;                                \
    }

    int i = 0;
    for (; i + 4 <= cnt; i += 4) {
        int4 ss = __ldg((const int4*)(row + i));    // broadcast, 1 LDG / 4 edges
        AGG_EDGE(ss.x); AGG_EDGE(ss.y); AGG_EDGE(ss.z); AGG_EDGE(ss.w);
    }
    for (; i < cnt; ++i) AGG_EDGE(row[i]);
#undef AGG_EDGE

    float4 bv = *(const float4*)(bias + lane * 4);
    float4 rr0, rr1;
    rr0.x = fmaxf(din * a0.x + bv.x, 0.f);
    rr0.y = fmaxf(din * a0.y + bv.y, 0.f);
    rr0.z = fmaxf(din * a0.z + bv.z, 0.f);
    rr0.w = fmaxf(din * a0.w + bv.w, 0.f);
    rr1.x = fmaxf(din * a1.x + bv.x, 0.f);
    rr1.y = fmaxf(din * a1.y + bv.y, 0.f);
    rr1.z = fmaxf(din * a1.z + bv.z, 0.f);
    rr1.w = fmaxf(din * a1.w + bv.w, 0.f);

    float4* o4 = (float4*)g_buf1;
    o4[base + lane] = rr0;
    o4[base + 32 + lane] = rr1;

    int ch = lane * 4;
    atomicAdd(&ssum[ch + 0], rr0.x + rr1.x);
    atomicAdd(&ssum[ch + 1], rr0.y + rr1.y);
    atomicAdd(&ssum[ch + 2], rr0.z + rr1.z);
    atomicAdd(&ssum[ch + 3], rr0.w + rr1.w);
    atomicAdd(&ssq[ch + 0], rr0.x * rr0.x + rr1.x * rr1.x);
    atomicAdd(&ssq[ch + 1], rr0.y * rr0.y + rr1.y * rr1.y);
    atomicAdd(&ssq[ch + 2], rr0.z * rr0.z + rr1.z * rr1.z);
    atomicAdd(&ssq[ch + 3], rr0.w * rr0.w + rr1.w * rr1.w);
    __syncthreads();
    if (tid < HH) {
        atomicAdd(&bnsum[tid], ssum[tid]);
        atomicAdd(&bnsq[tid], ssq[tid]);
    }
}

// ---------------- classifier (computes BN2 affine in preamble) ---------------
__global__ void __launch_bounds__(256) k_cls(const float* __restrict__ Wc,
                                             const float* __restrict__ bc,
                                             const float* __restrict__ gamma,
                                             const float* __restrict__ beta,
                                             float* __restrict__ out) {
    __shared__ float sW[HH * OO];
    __shared__ float sb[OO];
    __shared__ float sSc[HH], sSh[HH];
    for (int i = threadIdx.x; i < HH * OO; i += blockDim.x) sW[i] = Wc[i];
    if (threadIdx.x < OO) sb[threadIdx.x] = bc[threadIdx.x];
    if (threadIdx.x < HH) {
        float sc, sh;
        bn_coeff(g_bnsum2, g_bnsq2, gamma, beta, threadIdx.x, sc, sh);
        sSc[threadIdx.x] = sc;
        sSh[threadIdx.x] = sh;
    }
    __syncthreads();

    int warp = threadIdx.x >> 5;
    int lane = threadIdx.x & 31;
    int row = blockIdx.x * 8 + warp;
    if (row >= BBATCH * NN) return;

    int k = lane * 4;
    float4 v = *(const float4*)(g_buf1 + (long)row * HH + k);
    v.x = v.x * sSc[k + 0] + sSh[k + 0];
    v.y = v.y * sSc[k + 1] + sSh[k + 1];
    v.z = v.z * sSc[k + 2] + sSh[k + 2];
    v.w = v.w * sSc[k + 3] + sSh[k + 3];

    float p[OO];
#pragma unroll
    for (int c = 0; c < OO; c++) {
        p[c] = v.x * sW[(k + 0) * OO + c] + v.y * sW[(k + 1) * OO + c] +
               v.z * sW[(k + 2) * OO + c] + v.w * sW[(k + 3) * OO + c];
    }
#pragma unroll
    for (int c = 0; c < OO; c++) {
#pragma unroll
        for (int o = 16; o > 0; o >>= 1)
            p[c] += __shfl_xor_sync(0xffffffffu, p[c], o);
    }
    if (lane < OO) {
        int n = row >> 1, b = row & 1;
        out[((long)b * NN + n) * OO + lane] = p[lane] + sb[lane];
    }
}

// ---------------- launch -----------------------------------------------------
extern "C" void kernel_launch(void* const* d_in, const int* in_sizes, int n_in,
                              void* d_out, int out_size) {
    const float* x  = (const float*)d_in[0];
    const float* W1 = (const float*)d_in[1];
    const float* b1 = (const float*)d_in[2];
    const float* W2 = (const float*)d_in[3];
    const float* b2 = (const float*)d_in[4];
    const float* g1 = (const float*)d_in[5];
    const float* bt1 = (const float*)d_in[6];
    const float* g2 = (const float*)d_in[7];
    const float* bt2 = (const float*)d_in[8];
    const float* Wc = (const float*)d_in[9];
    const float* bc = (const float*)d_in[10];
    const void* ei = d_in[11];
    float* out = (float*)d_out;

    dim3 ggrid((NN + 127) / 128, BBATCH);   // 157 x 2, 256 threads

    // Fork: W1+W2 pack + layer-1 GEMM concurrent with graph build.
    cudaStream_t s1;
    cudaStreamCreateWithFlags(&s1, cudaStreamNonBlocking);
    cudaEvent_t ev0, ev1;
    cudaEventCreateWithFlags(&ev0, cudaEventDisableTiming);
    cudaEventCreateWithFlags(&ev1, cudaEventDisableTiming);

    cudaEventRecord(ev0, 0);
    cudaStreamWaitEvent(s1, ev0, 0);
    k_prepw<<<32, 128, 0, s1>>>(W1, W2);
    k_gemm_tc<0, 0, false><<<ggrid, 256, 0, s1>>>(x, nullptr, nullptr);
    cudaEventRecord(ev1, s1);

    // main stream: graph build (+ BN stat buffer zeroing)
    k_zero<<<(NN + 255) / 256, 256>>>((const int*)ei);
    k_fill_ell<<<EE / 1024, 256>>>(ei);
    k_dinv<<<(NN + 255) / 256, 256>>>();

    // join
    cudaStreamWaitEvent(0, ev1, 0);

    // layer 1 tail (stats -> g_bnsum1/g_bnsq1)
    k_aggbn<1><<<NN / 8, 256>>>(b1);

    // layer 2 (BN1 affine computed per-block from raw stats)
    k_gemm_tc<1, 1, true><<<ggrid, 256>>>(nullptr, g1, bt1);
    k_aggbn<2><<<NN / 8, 256>>>(b2);

    // classifier (BN2 affine computed per-block from raw stats)
    k_cls<<<(BBATCH * NN + 7) / 8, 256>>>(Wc, bc, g2, bt2, out);
}

// round 12
// speedup vs baseline: 1.4490x; 1.4490x over previous
#include <cuda_runtime.h>
#include <cstdint>

#define NN 20000
#define EE 640000
#define BBATCH 2
#define HH 128
#define OO 10
#define PAD 192

// ---------------- scratch ----------------------------------------------------
__device__ int   g_fill[NN];          // degree counter / final degree
__device__ int   g_ell[NN * PAD];     // ELL adjacency (src ids)
__device__ float g_dinv[NN];
__device__ int   g_is64;
__device__ __align__(16) float g_buf0[BBATCH * NN * HH];
__device__ __align__(16) float g_buf1[BBATCH * NN * HH];
__device__ float g_bnsum1[HH], g_bnsq1[HH];   // layer-1 BN stats
__device__ float g_bnsum2[HH], g_bnsq2[HH];   // layer-2 BN stats
// W fragment packs (tf32 hi/lo): 16 k-chunks x 1024 floats (16 nt x 32 lanes x 2 regs)
__device__ __align__(16) float g_fW1hi[16384];
__device__ __align__(16) float g_fW1lo[16384];
__device__ __align__(16) float g_fW2hi[16384];
__device__ __align__(16) float g_fW2lo[16384];

// ---------------- helpers ----------------------------------------------------
__device__ __forceinline__ unsigned f2tf(float x) {
    unsigned r;
    asm("cvt.rna.tf32.f32 %0, %1;" : "=r"(r) : "f"(x));
    return r;
}

// B fragment (m16n8k8 tf32, PTX spec): lane=(n&7)*4+(k&3), reg=(k&7)>>2
__device__ __forceinline__ int fragIdx(int k, int n) {
    int kt = k >> 3, kk = k & 7;
    int t = kk & 3, r = kk >> 2;
    int nt = n >> 3, g = n & 7;
    int lane = (g << 2) | t;
    return ((kt * 16 + nt) * 32 + lane) * 2 + r;   // chunk stride 1024
}

__device__ __forceinline__ void mma_tf32(float* d, unsigned a0, unsigned a1,
                                         unsigned a2, unsigned a3,
                                         unsigned b0, unsigned b1) {
    asm volatile(
        "mma.sync.aligned.m16n8k8.row.col.f32.tf32.tf32.f32 "
        "{%0,%1,%2,%3},{%4,%5,%6,%7},{%8,%9},{%0,%1,%2,%3};\n"
        : "+f"(d[0]), "+f"(d[1]), "+f"(d[2]), "+f"(d[3])
        : "r"(a0), "r"(a1), "r"(a2), "r"(a3), "r"(b0), "r"(b1));
}

__device__ __forceinline__ int edge_at2(const void* eiv, int is64, long idx) {
    return is64 ? (int)((const long long*)eiv)[idx] : ((const int*)eiv)[idx];
}

// compute BN affine coeffs for channel c from raw stats
__device__ __forceinline__ void bn_coeff(const float* bnsum, const float* bnsq,
                                         const float* gamma, const float* beta,
                                         int c, float& sc, float& sh) {
    float cnt = (float)(BBATCH * NN);
    float mean = bnsum[c] / cnt;
    float var = bnsq[c] / cnt - mean * mean;
    float inv = rsqrtf(var + 1e-5f);
    sc = gamma[c] * inv;
    sh = beta[c] - mean * sc;
}

// ---------------- graph prep -------------------------------------------------
__global__ void k_zero(const int* __restrict__ ei32) {
    int i = blockIdx.x * blockDim.x + threadIdx.x;
    if (i < NN) g_fill[i] = 0;
    if (i < HH) {
        g_bnsum1[i] = 0.f; g_bnsq1[i] = 0.f;
        g_bnsum2[i] = 0.f; g_bnsq2[i] = 0.f;
    }
    if (blockIdx.x == 0 && threadIdx.x < 32) {
        int lane = threadIdx.x;
        int nz = (ei32[2 * lane + 1] != 0) | (ei32[2 * (lane + 32) + 1] != 0);
        unsigned m = __ballot_sync(0xffffffffu, nz);
        if (lane == 0) g_is64 = (m == 0);
    }
}

__global__ void k_fill_ell(const void* __restrict__ eiv) {
    int is64 = g_is64;
    long e0 = (long)(blockIdx.x * blockDim.x + threadIdx.x) * 4;   // grid covers EE exactly
    int s[4], d[4];
#pragma unroll
    for (int i = 0; i < 4; i++) {
        s[i] = edge_at2(eiv, is64, e0 + i);
        d[i] = edge_at2(eiv, is64, (long)EE + e0 + i);
    }
#pragma unroll
    for (int i = 0; i < 4; i++) {
        int p = atomicAdd(&g_fill[d[i]], 1);
        g_ell[d[i] * PAD + p] = s[i];
    }
}

__global__ void k_dinv() {
    int i = blockIdx.x * blockDim.x + threadIdx.x;
    if (i < NN) g_dinv[i] = rsqrtf((float)(g_fill[i] + 1));   // +1 = self loop
}

// ---------------- W1+W2 fragment pack (off critical path, fork stream) -------
__global__ void k_prepw(const float* __restrict__ W1, const float* __restrict__ W2) {
    int n = threadIdx.x;
    int blk = blockIdx.x;                 // 0..31: 0-15 W1, 16-31 W2
    const float* W = (blk < 16) ? W1 : W2;
    float* fh = (blk < 16) ? g_fW1hi : g_fW2hi;
    float* fl = (blk < 16) ? g_fW1lo : g_fW2lo;
    int k0 = (blk & 15) * 8;
    for (int k = k0; k < k0 + 8; k++) {
        float w = W[k * HH + n];
        unsigned hi = f2tf(w);
        unsigned lo = f2tf(w - __uint_as_float(hi));
        int idx = fragIdx(k, n);
        fh[idx] = __uint_as_float(hi);
        fl[idx] = __uint_as_float(lo);
    }
}

// ---------------- tensor-core GEMM: C = affine(A) @ Wfrag --------------------
// R10 configuration: smem double-buffered B, 256 threads, 2D grid.
// ALAYOUT 0: A row = b*NN+n (external x); 1: row = n*2+b (g_buf1)
template <int ALAYOUT, int WSEL, bool AFFINE>
__global__ void __launch_bounds__(256) k_gemm_tc(const float* __restrict__ Ain,
                                                 const float* __restrict__ gamma,
                                                 const float* __restrict__ beta) {
    __shared__ __align__(16) float sHi[2][1024];
    __shared__ __align__(16) float sLo[2][1024];
    __shared__ float sSc[HH], sSh[HH];
    const float* A = ALAYOUT ? (const float*)g_buf1 : Ain;
    const float* fH = WSEL ? g_fW2hi : g_fW1hi;
    const float* fL = WSEL ? g_fW2lo : g_fW1lo;

    int tid = threadIdx.x, lane = tid & 31, warp = tid >> 5;
    int b = blockIdx.y;
    int rowBase = blockIdx.x * 128;
    int g = lane >> 2, t = lane & 3;
    int r0 = rowBase + warp * 16 + g;
    int r1 = r0 + 8;
    int rc0 = r0 < NN ? r0 : NN - 1;
    int rc1 = r1 < NN ? r1 : NN - 1;
    long a0b = ALAYOUT ? ((long)rc0 * 2 + b) * HH : ((long)b * NN + rc0) * HH;
    long a1b = ALAYOUT ? ((long)rc1 * 2 + b) * HH : ((long)b * NN + rc1) * HH;

    if (AFFINE && tid < HH) {
        float sc, sh;
        bn_coeff(g_bnsum1, g_bnsq1, gamma, beta, tid, sc, sh);
        sSc[tid] = sc;
        sSh[tid] = sh;
    }

    float acc[16][4];
#pragma unroll
    for (int i = 0; i < 16; i++)
#pragma unroll
        for (int j = 0; j < 4; j++) acc[i][j] = 0.f;

    int ld = tid * 4;
    *(float4*)&sHi[0][ld] = *(const float4*)&fH[ld];
    *(float4*)&sLo[0][ld] = *(const float4*)&fL[ld];

    // A prefetch for chunk 0
    float fa0 = __ldg(A + a0b + t);
    float fa1 = __ldg(A + a1b + t);
    float fa2 = __ldg(A + a0b + t + 4);
    float fa3 = __ldg(A + a1b + t + 4);
    __syncthreads();

    for (int c = 0; c < 16; c++) {
        int cur = c & 1;
        float4 nh, nl;
        float nf0, nf1, nf2, nf3;
        if (c < 15) {
            int k1 = (c + 1) * 8;
            nf0 = __ldg(A + a0b + k1 + t);
            nf1 = __ldg(A + a1b + k1 + t);
            nf2 = __ldg(A + a0b + k1 + t + 4);
            nf3 = __ldg(A + a1b + k1 + t + 4);
            nh = *(const float4*)&fH[(c + 1) * 1024 + ld];
            nl = *(const float4*)&fL[(c + 1) * 1024 + ld];
        }
        int k0 = c * 8;
        if (AFFINE) {
            float s0 = sSc[k0 + t], h0 = sSh[k0 + t];
            float s4 = sSc[k0 + t + 4], h4 = sSh[k0 + t + 4];
            fa0 = fa0 * s0 + h0;
            fa1 = fa1 * s0 + h0;
            fa2 = fa2 * s4 + h4;
            fa3 = fa3 * s4 + h4;
        }
        // A frag (PTX spec): a0=(r0,t) a1=(r1,t) a2=(r0,t+4) a3=(r1,t+4)
        unsigned ah0 = f2tf(fa0), ah1 = f2tf(fa1), ah2 = f2tf(fa2), ah3 = f2tf(fa3);
        unsigned al0 = f2tf(fa0 - __uint_as_float(ah0));
        unsigned al1 = f2tf(fa1 - __uint_as_float(ah1));
        unsigned al2 = f2tf(fa2 - __uint_as_float(ah2));
        unsigned al3 = f2tf(fa3 - __uint_as_float(ah3));

#pragma unroll
        for (int nt = 0; nt < 16; nt++) {
            float2 bh = *(const float2*)&sHi[cur][nt * 64 + lane * 2];
            float2 bl = *(const float2*)&sLo[cur][nt * 64 + lane * 2];
            unsigned bh0 = __float_as_uint(bh.x), bh1 = __float_as_uint(bh.y);
            unsigned bl0 = __float_as_uint(bl.x), bl1 = __float_as_uint(bl.y);
            mma_tf32(acc[nt], ah0, ah1, ah2, ah3, bh0, bh1);
            mma_tf32(acc[nt], al0, al1, al2, al3, bh0, bh1);
            mma_tf32(acc[nt], ah0, ah1, ah2, ah3, bl0, bl1);
        }
        __syncthreads();
        if (c < 15) {
            int nxt = cur ^ 1;
            *(float4*)&sHi[nxt][ld] = nh;
            *(float4*)&sLo[nxt][ld] = nl;
            fa0 = nf0; fa1 = nf1; fa2 = nf2; fa3 = nf3;
        }
        __syncthreads();
    }

#pragma unroll
    for (int nt = 0; nt < 16; nt++) {
        int col = nt * 8 + 2 * t;
        if (r0 < NN)
            *(float2*)&g_buf0[((long)r0 * 2 + b) * HH + col] =
                make_float2(acc[nt][0], acc[nt][1]);
        if (r1 < NN)
            *(float2*)&g_buf0[((long)r1 * 2 + b) * HH + col] =
                make_float2(acc[nt][2], acc[nt][3]);
    }
}

// ---------------- aggregation + fused BN stats (per-layer buffers) -----------
template <int LAYER>
__global__ void __launch_bounds__(256) k_aggbn(const float* __restrict__ bias) {
    float* bnsum = (LAYER == 1) ? g_bnsum1 : g_bnsum2;
    float* bnsq  = (LAYER == 1) ? g_bnsq1 : g_bnsq2;
    __shared__ float ssum[HH], ssq[HH];
    int tid = threadIdx.x;
    if (tid < HH) { ssum[tid] = 0.f; ssq[tid] = 0.f; }
    __syncthreads();

    int node = (blockIdx.x * blockDim.x + tid) >> 5;   // grid*8 == NN exactly
    int lane = tid & 31;
    float din = g_dinv[node];

    const float4* h4 = (const float4*)g_buf0;
    long base = (long)node * 64;
    float4 v0 = __ldg(&h4[base + lane]);
    float4 v1 = __ldg(&h4[base + 32 + lane]);
    float4 a0, a1;
    a0.x = din * v0.x; a0.y = din * v0.y; a0.z = din * v0.z; a0.w = din * v0.w;
    a1.x = din * v1.x; a1.y = din * v1.y; a1.z = din * v1.z; a1.w = din * v1.w;

    int cnt = g_fill[node];
    const int* row = g_ell + node * PAD;

#define AGG_EDGE(S)                                                        \
    {                                                                      \
        int _s = (S);                                                      \
        float w = __ldg(&g_dinv[_s]);                                      \
        long sb = (long)_s * 64;                                           \
        float4 u0 = __ldg(&h4[sb + lane]);                                 \
        float4 u1 = __ldg(&h4[sb + 32 + lane]);                            \
        a0.x += w * u0.x; a0.y += w * u0.y;                                \
        a0.z += w * u0.z; a0.w += w * u0.w;                                \
        a1.x += w * u1.x; a1.y += w * u1.y;                                \
        a1.z += w * u1.z; a1.w += w * u1.w;                                \
    }

    int i = 0;
    for (; i + 4 <= cnt; i += 4) {
        int4 ss = __ldg((const int4*)(row + i));    // broadcast, 1 LDG / 4 edges
        AGG_EDGE(ss.x); AGG_EDGE(ss.y); AGG_EDGE(ss.z); AGG_EDGE(ss.w);
    }
    for (; i < cnt; ++i) AGG_EDGE(row[i]);
#undef AGG_EDGE

    float4 bv = *(const float4*)(bias + lane * 4);
    float4 rr0, rr1;
    rr0.x = fmaxf(din * a0.x + bv.x, 0.f);
    rr0.y = fmaxf(din * a0.y + bv.y, 0.f);
    rr0.z = fmaxf(din * a0.z + bv.z, 0.f);
    rr0.w = fmaxf(din * a0.w + bv.w, 0.f);
    rr1.x = fmaxf(din * a1.x + bv.x, 0.f);
    rr1.y = fmaxf(din * a1.y + bv.y, 0.f);
    rr1.z = fmaxf(din * a1.z + bv.z, 0.f);
    rr1.w = fmaxf(din * a1.w + bv.w, 0.f);

    float4* o4 = (float4*)g_buf1;
    o4[base + lane] = rr0;
    o4[base + 32 + lane] = rr1;

    int ch = lane * 4;
    atomicAdd(&ssum[ch + 0], rr0.x + rr1.x);
    atomicAdd(&ssum[ch + 1], rr0.y + rr1.y);
    atomicAdd(&ssum[ch + 2], rr0.z + rr1.z);
    atomicAdd(&ssum[ch + 3], rr0.w + rr1.w);
    atomicAdd(&ssq[ch + 0], rr0.x * rr0.x + rr1.x * rr1.x);
    atomicAdd(&ssq[ch + 1], rr0.y * rr0.y + rr1.y * rr1.y);
    atomicAdd(&ssq[ch + 2], rr0.z * rr0.z + rr1.z * rr1.z);
    atomicAdd(&ssq[ch + 3], rr0.w * rr0.w + rr1.w * rr1.w);
    __syncthreads();
    if (tid < HH) {
        atomicAdd(&bnsum[tid], ssum[tid]);
        atomicAdd(&bnsq[tid], ssq[tid]);
    }
}

// ---------------- classifier (computes BN2 affine in preamble) ---------------
__global__ void __launch_bounds__(256) k_cls(const float* __restrict__ Wc,
                                             const float* __restrict__ bc,
                                             const float* __restrict__ gamma,
                                             const float* __restrict__ beta,
                                             float* __restrict__ out) {
    __shared__ float sW[HH * OO];
    __shared__ float sb[OO];
    __shared__ float sSc[HH], sSh[HH];
    for (int i = threadIdx.x; i < HH * OO; i += blockDim.x) sW[i] = Wc[i];
    if (threadIdx.x < OO) sb[threadIdx.x] = bc[threadIdx.x];
    if (threadIdx.x < HH) {
        float sc, sh;
        bn_coeff(g_bnsum2, g_bnsq2, gamma, beta, threadIdx.x, sc, sh);
        sSc[threadIdx.x] = sc;
        sSh[threadIdx.x] = sh;
    }
    __syncthreads();

    int warp = threadIdx.x >> 5;
    int lane = threadIdx.x & 31;
    int row = blockIdx.x * 8 + warp;
    if (row >= BBATCH * NN) return;

    int k = lane * 4;
    float4 v = *(const float4*)(g_buf1 + (long)row * HH + k);
    v.x = v.x * sSc[k + 0] + sSh[k + 0];
    v.y = v.y * sSc[k + 1] + sSh[k + 1];
    v.z = v.z * sSc[k + 2] + sSh[k + 2];
    v.w = v.w * sSc[k + 3] + sSh[k + 3];

    float p[OO];
#pragma unroll
    for (int c = 0; c < OO; c++) {
        p[c] = v.x * sW[(k + 0) * OO + c] + v.y * sW[(k + 1) * OO + c] +
               v.z * sW[(k + 2) * OO + c] + v.w * sW[(k + 3) * OO + c];
    }
#pragma unroll
    for (int c = 0; c < OO; c++) {
#pragma unroll
        for (int o = 16; o > 0; o >>= 1)
            p[c] += __shfl_xor_sync(0xffffffffu, p[c], o);
    }
    if (lane < OO) {
        int n = row >> 1, b = row & 1;
        out[((long)b * NN + n) * OO + lane] = p[lane] + sb[lane];
    }
}

// ---------------- launch -----------------------------------------------------
extern "C" void kernel_launch(void* const* d_in, const int* in_sizes, int n_in,
                              void* d_out, int out_size) {
    const float* x  = (const float*)d_in[0];
    const float* W1 = (const float*)d_in[1];
    const float* b1 = (const float*)d_in[2];
    const float* W2 = (const float*)d_in[3];
    const float* b2 = (const float*)d_in[4];
    const float* g1 = (const float*)d_in[5];
    const float* bt1 = (const float*)d_in[6];
    const float* g2 = (const float*)d_in[7];
    const float* bt2 = (const float*)d_in[8];
    const float* Wc = (const float*)d_in[9];
    const float* bc = (const float*)d_in[10];
    const void* ei = d_in[11];
    float* out = (float*)d_out;

    dim3 ggrid((NN + 127) / 128, BBATCH);   // 157 x 2, 256 threads

    // Fork: W1+W2 pack + layer-1 GEMM concurrent with graph build.
    cudaStream_t s1;
    cudaStreamCreateWithFlags(&s1, cudaStreamNonBlocking);
    cudaEvent_t ev0, ev1;
    cudaEventCreateWithFlags(&ev0, cudaEventDisableTiming);
    cudaEventCreateWithFlags(&ev1, cudaEventDisableTiming);

    cudaEventRecord(ev0, 0);
    cudaStreamWaitEvent(s1, ev0, 0);
    k_prepw<<<32, 128, 0, s1>>>(W1, W2);
    k_gemm_tc<0, 0, false><<<ggrid, 256, 0, s1>>>(x, nullptr, nullptr);
    cudaEventRecord(ev1, s1);

    // main stream: graph build (+ BN stat buffer zeroing)
    k_zero<<<(NN + 255) / 256, 256>>>((const int*)ei);
    k_fill_ell<<<EE / 1024, 256>>>(ei);
    k_dinv<<<(NN + 255) / 256, 256>>>();

    // join
    cudaStreamWaitEvent(0, ev1, 0);

    // layer 1 tail (stats -> g_bnsum1/g_bnsq1)
    k_aggbn<1><<<NN / 8, 256>>>(b1);

    // layer 2 (BN1 affine computed per-block from raw stats)
    k_gemm_tc<1, 1, true><<<ggrid, 256>>>(nullptr, g1, bt1);
    k_aggbn<2><<<NN / 8, 256>>>(b2);

    // classifier (BN2 affine computed per-block from raw stats)
    k_cls<<<(BBATCH * NN + 7) / 8, 256>>>(Wc, bc, g2, bt2, out);
}

// round 13
// speedup vs baseline: 1.5560x; 1.0738x over previous
#include <cuda_runtime.h>
#include <cstdint>

#define NN 20000
#define EE 640000
#define BBATCH 2
#define HH 128
#define OO 10
#define PAD 192
#define ROWS (BBATCH * NN)

// ---------------- scratch ----------------------------------------------------
__device__ int   g_fill[NN];          // degree counter / final degree
__device__ int   g_ell[NN * PAD];     // ELL adjacency (src ids)
__device__ float g_dinv[NN];
__device__ int   g_is64;
__device__ __align__(16) float g_buf0[ROWS * HH];
__device__ __align__(16) float g_buf1[ROWS * HH];
__device__ float g_bnsum1[HH], g_bnsq1[HH];   // layer-1 BN stats
__device__ float g_bnsum2[HH], g_bnsq2[HH];   // layer-2 BN stats
// W fragment packs (tf32 hi/lo): 16 k-chunks x 1024 floats (16 nt x 32 lanes x 2 regs)
__device__ __align__(16) float g_fW1hi[16384];
__device__ __align__(16) float g_fW1lo[16384];
__device__ __align__(16) float g_fW2hi[16384];
__device__ __align__(16) float g_fW2lo[16384];
// Wc fragments (tf32 hi/lo): 16 kt x 2 nt x 32 lanes x 2 regs = 2048 floats
__device__ __align__(16) float g_fWchi[2048];
__device__ __align__(16) float g_fWclo[2048];

// ---------------- helpers ----------------------------------------------------
__device__ __forceinline__ unsigned f2tf(float x) {
    unsigned r;
    asm("cvt.rna.tf32.f32 %0, %1;" : "=r"(r) : "f"(x));
    return r;
}

// B fragment (m16n8k8 tf32, PTX spec): lane=(n&7)*4+(k&3), reg=(k&7)>>2
__device__ __forceinline__ int fragIdx(int k, int n) {
    int kt = k >> 3, kk = k & 7;
    int t = kk & 3, r = kk >> 2;
    int nt = n >> 3, g = n & 7;
    int lane = (g << 2) | t;
    return ((kt * 16 + nt) * 32 + lane) * 2 + r;   // chunk stride 1024
}

// same mapping, 2 n-tiles wide (classifier): chunk stride 128
__device__ __forceinline__ int fragIdxC(int k, int n) {
    int kt = k >> 3, kk = k & 7;
    int t = kk & 3, r = kk >> 2;
    int nt = n >> 3, g = n & 7;
    int lane = (g << 2) | t;
    return ((kt * 2 + nt) * 32 + lane) * 2 + r;
}

__device__ __forceinline__ void mma_tf32(float* d, unsigned a0, unsigned a1,
                                         unsigned a2, unsigned a3,
                                         unsigned b0, unsigned b1) {
    asm volatile(
        "mma.sync.aligned.m16n8k8.row.col.f32.tf32.tf32.f32 "
        "{%0,%1,%2,%3},{%4,%5,%6,%7},{%8,%9},{%0,%1,%2,%3};\n"
        : "+f"(d[0]), "+f"(d[1]), "+f"(d[2]), "+f"(d[3])
        : "r"(a0), "r"(a1), "r"(a2), "r"(a3), "r"(b0), "r"(b1));
}

__device__ __forceinline__ int edge_at2(const void* eiv, int is64, long idx) {
    return is64 ? (int)((const long long*)eiv)[idx] : ((const int*)eiv)[idx];
}

// compute BN affine coeffs for channel c from raw stats
__device__ __forceinline__ void bn_coeff(const float* bnsum, const float* bnsq,
                                         const float* gamma, const float* beta,
                                         int c, float& sc, float& sh) {
    float cnt = (float)ROWS;
    float mean = bnsum[c] / cnt;
    float var = bnsq[c] / cnt - mean * mean;
    float inv = rsqrtf(var + 1e-5f);
    sc = gamma[c] * inv;
    sh = beta[c] - mean * sc;
}

// ---------------- graph prep -------------------------------------------------
__global__ void k_zero(const int* __restrict__ ei32) {
    int i = blockIdx.x * blockDim.x + threadIdx.x;
    if (i < NN) g_fill[i] = 0;
    if (i < HH) {
        g_bnsum1[i] = 0.f; g_bnsq1[i] = 0.f;
        g_bnsum2[i] = 0.f; g_bnsq2[i] = 0.f;
    }
    if (blockIdx.x == 0 && threadIdx.x < 32) {
        int lane = threadIdx.x;
        int nz = (ei32[2 * lane + 1] != 0) | (ei32[2 * (lane + 32) + 1] != 0);
        unsigned m = __ballot_sync(0xffffffffu, nz);
        if (lane == 0) g_is64 = (m == 0);
    }
}

__global__ void k_fill_ell(const void* __restrict__ eiv) {
    int is64 = g_is64;
    long e0 = (long)(blockIdx.x * blockDim.x + threadIdx.x) * 4;   // grid covers EE exactly
    int s[4], d[4];
#pragma unroll
    for (int i = 0; i < 4; i++) {
        s[i] = edge_at2(eiv, is64, e0 + i);
        d[i] = edge_at2(eiv, is64, (long)EE + e0 + i);
    }
#pragma unroll
    for (int i = 0; i < 4; i++) {
        int p = atomicAdd(&g_fill[d[i]], 1);
        g_ell[d[i] * PAD + p] = s[i];
    }
}

__global__ void k_dinv() {
    int i = blockIdx.x * blockDim.x + threadIdx.x;
    if (i < NN) g_dinv[i] = rsqrtf((float)(g_fill[i] + 1));   // +1 = self loop
}

// ---------------- W1+W2+Wc fragment pack (off critical path, fork stream) ----
__global__ void k_prepw(const float* __restrict__ W1, const float* __restrict__ W2,
                        const float* __restrict__ Wc) {
    int blk = blockIdx.x;                 // 0-15 W1, 16-31 W2, 32-35 Wc
    if (blk < 32) {
        int n = threadIdx.x;
        const float* W = (blk < 16) ? W1 : W2;
        float* fh = (blk < 16) ? g_fW1hi : g_fW2hi;
        float* fl = (blk < 16) ? g_fW1lo : g_fW2lo;
        int k0 = (blk & 15) * 8;
        for (int k = k0; k < k0 + 8; k++) {
            float w = W[k * HH + n];
            unsigned hi = f2tf(w);
            unsigned lo = f2tf(w - __uint_as_float(hi));
            int idx = fragIdx(k, n);
            fh[idx] = __uint_as_float(hi);
            fl[idx] = __uint_as_float(lo);
        }
    } else {
        // Wc pack: 4 blocks x (8k x 16n threads), each covers 32 k values
        int n = threadIdx.x & 15;
        int kl = threadIdx.x >> 4;        // 0..7
        int kbase = (blk - 32) * 32;
        for (int kk = 0; kk < 4; kk++) {
            int k = kbase + kk * 8 + kl;
            float w = (n < OO) ? Wc[k * OO + n] : 0.f;
            unsigned hi = f2tf(w);
            unsigned lo = f2tf(w - __uint_as_float(hi));
            int idx = fragIdxC(k, n);
            g_fWchi[idx] = __uint_as_float(hi);
            g_fWclo[idx] = __uint_as_float(lo);
        }
    }
}

// ---------------- tensor-core GEMM: C = affine(A) @ Wfrag --------------------
// smem double-buffered B, 256 threads, 2D grid (x: row tiles, y: batch).
// ALAYOUT 0: A row = b*NN+n (external x); 1: row = n*2+b (g_buf1)
template <int ALAYOUT, int WSEL, bool AFFINE>
__global__ void __launch_bounds__(256) k_gemm_tc(const float* __restrict__ Ain,
                                                 const float* __restrict__ gamma,
                                                 const float* __restrict__ beta) {
    __shared__ __align__(16) float sHi[2][1024];
    __shared__ __align__(16) float sLo[2][1024];
    __shared__ float sSc[HH], sSh[HH];
    const float* A = ALAYOUT ? (const float*)g_buf1 : Ain;
    const float* fH = WSEL ? g_fW2hi : g_fW1hi;
    const float* fL = WSEL ? g_fW2lo : g_fW1lo;

    int tid = threadIdx.x, lane = tid & 31, warp = tid >> 5;
    int b = blockIdx.y;
    int rowBase = blockIdx.x * 128;
    int g = lane >> 2, t = lane & 3;
    int r0 = rowBase + warp * 16 + g;
    int r1 = r0 + 8;
    int rc0 = r0 < NN ? r0 : NN - 1;
    int rc1 = r1 < NN ? r1 : NN - 1;
    long a0b = ALAYOUT ? ((long)rc0 * 2 + b) * HH : ((long)b * NN + rc0) * HH;
    long a1b = ALAYOUT ? ((long)rc1 * 2 + b) * HH : ((long)b * NN + rc1) * HH;

    if (AFFINE && tid < HH) {
        float sc, sh;
        bn_coeff(g_bnsum1, g_bnsq1, gamma, beta, tid, sc, sh);
        sSc[tid] = sc;
        sSh[tid] = sh;
    }

    float acc[16][4];
#pragma unroll
    for (int i = 0; i < 16; i++)
#pragma unroll
        for (int j = 0; j < 4; j++) acc[i][j] = 0.f;

    int ld = tid * 4;
    *(float4*)&sHi[0][ld] = *(const float4*)&fH[ld];
    *(float4*)&sLo[0][ld] = *(const float4*)&fL[ld];

    // A prefetch for chunk 0
    float fa0 = __ldg(A + a0b + t);
    float fa1 = __ldg(A + a1b + t);
    float fa2 = __ldg(A + a0b + t + 4);
    float fa3 = __ldg(A + a1b + t + 4);
    __syncthreads();

    for (int c = 0; c < 16; c++) {
        int cur = c & 1;
        float4 nh, nl;
        float nf0, nf1, nf2, nf3;
        if (c < 15) {
            int k1 = (c + 1) * 8;
            nf0 = __ldg(A + a0b + k1 + t);
            nf1 = __ldg(A + a1b + k1 + t);
            nf2 = __ldg(A + a0b + k1 + t + 4);
            nf3 = __ldg(A + a1b + k1 + t + 4);
            nh = *(const float4*)&fH[(c + 1) * 1024 + ld];
            nl = *(const float4*)&fL[(c + 1) * 1024 + ld];
        }
        int k0 = c * 8;
        if (AFFINE) {
            float s0 = sSc[k0 + t], h0 = sSh[k0 + t];
            float s4 = sSc[k0 + t + 4], h4 = sSh[k0 + t + 4];
            fa0 = fa0 * s0 + h0;
            fa1 = fa1 * s0 + h0;
            fa2 = fa2 * s4 + h4;
            fa3 = fa3 * s4 + h4;
        }
        // A frag (PTX spec): a0=(r0,t) a1=(r1,t) a2=(r0,t+4) a3=(r1,t+4)
        unsigned ah0 = f2tf(fa0), ah1 = f2tf(fa1), ah2 = f2tf(fa2), ah3 = f2tf(fa3);
        unsigned al0 = f2tf(fa0 - __uint_as_float(ah0));
        unsigned al1 = f2tf(fa1 - __uint_as_float(ah1));
        unsigned al2 = f2tf(fa2 - __uint_as_float(ah2));
        unsigned al3 = f2tf(fa3 - __uint_as_float(ah3));

#pragma unroll
        for (int nt = 0; nt < 16; nt++) {
            float2 bh = *(const float2*)&sHi[cur][nt * 64 + lane * 2];
            float2 bl = *(const float2*)&sLo[cur][nt * 64 + lane * 2];
            unsigned bh0 = __float_as_uint(bh.x), bh1 = __float_as_uint(bh.y);
            unsigned bl0 = __float_as_uint(bl.x), bl1 = __float_as_uint(bl.y);
            mma_tf32(acc[nt], ah0, ah1, ah2, ah3, bh0, bh1);
            mma_tf32(acc[nt], al0, al1, al2, al3, bh0, bh1);
            mma_tf32(acc[nt], ah0, ah1, ah2, ah3, bl0, bl1);
        }
        __syncthreads();
        if (c < 15) {
            int nxt = cur ^ 1;
            *(float4*)&sHi[nxt][ld] = nh;
            *(float4*)&sLo[nxt][ld] = nl;
            fa0 = nf0; fa1 = nf1; fa2 = nf2; fa3 = nf3;
        }
        __syncthreads();
    }

#pragma unroll
    for (int nt = 0; nt < 16; nt++) {
        int col = nt * 8 + 2 * t;
        if (r0 < NN)
            *(float2*)&g_buf0[((long)r0 * 2 + b) * HH + col] =
                make_float2(acc[nt][0], acc[nt][1]);
        if (r1 < NN)
            *(float2*)&g_buf0[((long)r1 * 2 + b) * HH + col] =
                make_float2(acc[nt][2], acc[nt][3]);
    }
}

// ---------------- aggregation + fused BN stats (per-layer buffers) -----------
template <int LAYER>
__global__ void __launch_bounds__(256) k_aggbn(const float* __restrict__ bias) {
    float* bnsum = (LAYER == 1) ? g_bnsum1 : g_bnsum2;
    float* bnsq  = (LAYER == 1) ? g_bnsq1 : g_bnsq2;
    __shared__ float ssum[HH], ssq[HH];
    int tid = threadIdx.x;
    if (tid < HH) { ssum[tid] = 0.f; ssq[tid] = 0.f; }
    __syncthreads();

    int node = (blockIdx.x * blockDim.x + tid) >> 5;   // grid*8 == NN exactly
    int lane = tid & 31;
    float din = g_dinv[node];

    const float4* h4 = (const float4*)g_buf0;
    long base = (long)node * 64;
    float4 v0 = __ldg(&h4[base + lane]);
    float4 v1 = __ldg(&h4[base + 32 + lane]);
    float4 a0, a1;
    a0.x = din * v0.x; a0.y = din * v0.y; a0.z = din * v0.z; a0.w = din * v0.w;
    a1.x = din * v1.x; a1.y = din * v1.y; a1.z = din * v1.z; a1.w = din * v1.w;

    int cnt = g_fill[node];
    const int* row = g_ell + node * PAD;

#define AGG_EDGE(S)                                                        \
    {                                                                      \
        int _s = (S);                                                      \
        float w = __ldg(&g_dinv[_s]);                                      \
        long sb = (long)_s * 64;                                           \
        float4 u0 = __ldg(&h4[sb + lane]);                                 \
        float4 u1 = __ldg(&h4[sb + 32 + lane]);                            \
        a0.x += w * u0.x; a0.y += w * u0.y;                                \
        a0.z += w * u0.z; a0.w += w * u0.w;                                \
        a1.x += w * u1.x; a1.y += w * u1.y;                                \
        a1.z += w * u1.z; a1.w += w * u1.w;                                \
    }

    int i = 0;
    for (; i + 4 <= cnt; i += 4) {
        int4 ss = __ldg((const int4*)(row + i));    // broadcast, 1 LDG / 4 edges
        AGG_EDGE(ss.x); AGG_EDGE(ss.y); AGG_EDGE(ss.z); AGG_EDGE(ss.w);
    }
    for (; i < cnt; ++i) AGG_EDGE(row[i]);
#undef AGG_EDGE

    float4 bv = *(const float4*)(bias + lane * 4);
    float4 rr0, rr1;
    rr0.x = fmaxf(din * a0.x + bv.x, 0.f);
    rr0.y = fmaxf(din * a0.y + bv.y, 0.f);
    rr0.z = fmaxf(din * a0.z + bv.z, 0.f);
    rr0.w = fmaxf(din * a0.w + bv.w, 0.f);
    rr1.x = fmaxf(din * a1.x + bv.x, 0.f);
    rr1.y = fmaxf(din * a1.y + bv.y, 0.f);
    rr1.z = fmaxf(din * a1.z + bv.z, 0.f);
    rr1.w = fmaxf(din * a1.w + bv.w, 0.f);

    float4* o4 = (float4*)g_buf1;
    o4[base + lane] = rr0;
    o4[base + 32 + lane] = rr1;

    int ch = lane * 4;
    atomicAdd(&ssum[ch + 0], rr0.x + rr1.x);
    atomicAdd(&ssum[ch + 1], rr0.y + rr1.y);
    atomicAdd(&ssum[ch + 2], rr0.z + rr1.z);
    atomicAdd(&ssum[ch + 3], rr0.w + rr1.w);
    atomicAdd(&ssq[ch + 0], rr0.x * rr0.x + rr1.x * rr1.x);
    atomicAdd(&ssq[ch + 1], rr0.y * rr0.y + rr1.y * rr1.y);
    atomicAdd(&ssq[ch + 2], rr0.z * rr0.z + rr1.z * rr1.z);
    atomicAdd(&ssq[ch + 3], rr0.w * rr0.w + rr1.w * rr1.w);
    __syncthreads();
    if (tid < HH) {
        atomicAdd(&bnsum[tid], ssum[tid]);
        atomicAdd(&bnsq[tid], ssq[tid]);
    }
}

// ---------------- tensor-core classifier: out = affine(buf1) @ Wc + bc -------
// 40000-row GEMM over interleaved rows (r = n*2+b), 2 n-tiles (OO=10 pad 16).
__global__ void __launch_bounds__(256) k_cls_tc(const float* __restrict__ bc,
                                                const float* __restrict__ gamma,
                                                const float* __restrict__ beta,
                                                float* __restrict__ out) {
    __shared__ __align__(16) float sWh[2048], sWl[2048];
    __shared__ float sSc[HH], sSh[HH];
    __shared__ float sbc[16];
    int tid = threadIdx.x, lane = tid & 31, warp = tid >> 5;

    // stage all Wc fragments (8KB) once
    int ld = tid * 8;
    *(float4*)&sWh[ld]     = *(const float4*)&g_fWchi[ld];
    *(float4*)&sWh[ld + 4] = *(const float4*)&g_fWchi[ld + 4];
    *(float4*)&sWl[ld]     = *(const float4*)&g_fWclo[ld];
    *(float4*)&sWl[ld + 4] = *(const float4*)&g_fWclo[ld + 4];
    if (tid < HH) {
        float sc, sh;
        bn_coeff(g_bnsum2, g_bnsq2, gamma, beta, tid, sc, sh);
        sSc[tid] = sc;
        sSh[tid] = sh;
    }
    if (tid < 16) sbc[tid] = (tid < OO) ? bc[tid] : 0.f;

    int g = lane >> 2, t = lane & 3;
    int r0 = blockIdx.x * 128 + warp * 16 + g;
    int r1 = r0 + 8;
    int rc0 = r0 < ROWS ? r0 : ROWS - 1;
    int rc1 = r1 < ROWS ? r1 : ROWS - 1;
    const float* A = (const float*)g_buf1;
    long a0b = (long)rc0 * HH;
    long a1b = (long)rc1 * HH;

    float acc[2][4];
#pragma unroll
    for (int i = 0; i < 2; i++)
#pragma unroll
        for (int j = 0; j < 4; j++) acc[i][j] = 0.f;

    // A prefetch for chunk 0
    float fa0 = __ldg(A + a0b + t);
    float fa1 = __ldg(A + a1b + t);
    float fa2 = __ldg(A + a0b + t + 4);
    float fa3 = __ldg(A + a1b + t + 4);
    __syncthreads();

    for (int c = 0; c < 16; c++) {
        float nf0, nf1, nf2, nf3;
        if (c < 15) {
            int k1 = (c + 1) * 8;
            nf0 = __ldg(A + a0b + k1 + t);
            nf1 = __ldg(A + a1b + k1 + t);
            nf2 = __ldg(A + a0b + k1 + t + 4);
            nf3 = __ldg(A + a1b + k1 + t + 4);
        }
        int k0 = c * 8;
        float s0 = sSc[k0 + t], h0 = sSh[k0 + t];
        float s4 = sSc[k0 + t + 4], h4 = sSh[k0 + t + 4];
        fa0 = fa0 * s0 + h0;
        fa1 = fa1 * s0 + h0;
        fa2 = fa2 * s4 + h4;
        fa3 = fa3 * s4 + h4;

        unsigned ah0 = f2tf(fa0), ah1 = f2tf(fa1), ah2 = f2tf(fa2), ah3 = f2tf(fa3);
        unsigned al0 = f2tf(fa0 - __uint_as_float(ah0));
        unsigned al1 = f2tf(fa1 - __uint_as_float(ah1));
        unsigned al2 = f2tf(fa2 - __uint_as_float(ah2));
        unsigned al3 = f2tf(fa3 - __uint_as_float(ah3));

#pragma unroll
        for (int nt = 0; nt < 2; nt++) {
            int off = c * 128 + nt * 64 + lane * 2;
            float2 bh = *(const float2*)&sWh[off];
            float2 bl = *(const float2*)&sWl[off];
            unsigned bh0 = __float_as_uint(bh.x), bh1 = __float_as_uint(bh.y);
            unsigned bl0 = __float_as_uint(bl.x), bl1 = __float_as_uint(bl.y);
            mma_tf32(acc[nt], ah0, ah1, ah2, ah3, bh0, bh1);
            mma_tf32(acc[nt], al0, al1, al2, al3, bh0, bh1);
            mma_tf32(acc[nt], ah0, ah1, ah2, ah3, bl0, bl1);
        }
        if (c < 15) { fa0 = nf0; fa1 = nf1; fa2 = nf2; fa3 = nf3; }
    }

    // epilogue: out[(b*NN+n)*OO + col], r = n*2+b
#pragma unroll
    for (int nt = 0; nt < 2; nt++) {
        int col = nt * 8 + 2 * t;
        if (col + 1 < OO) {
            if (r0 < ROWS) {
                long o = ((long)(r0 & 1) * NN + (r0 >> 1)) * OO + col;
                out[o]     = acc[nt][0] + sbc[col];
                out[o + 1] = acc[nt][1] + sbc[col + 1];
            }
            if (r1 < ROWS) {
                long o = ((long)(r1 & 1) * NN + (r1 >> 1)) * OO + col;
                out[o]     = acc[nt][2] + sbc[col];
                out[o + 1] = acc[nt][3] + sbc[col + 1];
            }
        }
    }
}

// ---------------- launch -----------------------------------------------------
extern "C" void kernel_launch(void* const* d_in, const int* in_sizes, int n_in,
                              void* d_out, int out_size) {
    const float* x  = (const float*)d_in[0];
    const float* W1 = (const float*)d_in[1];
    const float* b1 = (const float*)d_in[2];
    const float* W2 = (const float*)d_in[3];
    const float* b2 = (const float*)d_in[4];
    const float* g1 = (const float*)d_in[5];
    const float* bt1 = (const float*)d_in[6];
    const float* g2 = (const float*)d_in[7];
    const float* bt2 = (const float*)d_in[8];
    const float* Wc = (const float*)d_in[9];
    const float* bc = (const float*)d_in[10];
    const void* ei = d_in[11];
    float* out = (float*)d_out;

    dim3 ggrid((NN + 127) / 128, BBATCH);   // 157 x 2, 256 threads

    // Fork: W pack + layer-1 GEMM concurrent with graph build.
    cudaStream_t s1;
    cudaStreamCreateWithFlags(&s1, cudaStreamNonBlocking);
    cudaEvent_t ev0, ev1;
    cudaEventCreateWithFlags(&ev0, cudaEventDisableTiming);
    cudaEventCreateWithFlags(&ev1, cudaEventDisableTiming);

    cudaEventRecord(ev0, 0);
    cudaStreamWaitEvent(s1, ev0, 0);
    k_prepw<<<36, 128, 0, s1>>>(W1, W2, Wc);
    k_gemm_tc<0, 0, false><<<ggrid, 256, 0, s1>>>(x, nullptr, nullptr);
    cudaEventRecord(ev1, s1);

    // main stream: graph build (+ BN stat buffer zeroing)
    k_zero<<<(NN + 255) / 256, 256>>>((const int*)ei);
    k_fill_ell<<<EE / 1024, 256>>>(ei);
    k_dinv<<<(NN + 255) / 256, 256>>>();

    // join
    cudaStreamWaitEvent(0, ev1, 0);

    // layer 1 tail (stats -> g_bnsum1/g_bnsq1)
    k_aggbn<1><<<NN / 8, 256>>>(b1);

    // layer 2 (BN1 affine computed per-block from raw stats)
    k_gemm_tc<1, 1, true><<<ggrid, 256>>>(nullptr, g1, bt1);
    k_aggbn<2><<<NN / 8, 256>>>(b2);

    // classifier: tensor-core GEMM, BN2 affine on A-path
    k_cls_tc<<<(ROWS + 127) / 128, 256>>>(bc, g2, bt2, out);
}

// round 14
// speedup vs baseline: 1.7844x; 1.1468x over previous
#include <cuda_runtime.h>
#include <cuda_bf16.h>
#include <cstdint>

#define NN 20000
#define EE 640000
#define BBATCH 2
#define HH 128
#define OO 10
#define PAD 192
#define ROWS (BBATCH * NN)

// ---------------- scratch ----------------------------------------------------
__device__ int   g_fill[NN];          // degree counter / final degree
__device__ int   g_ell[NN * PAD];     // ELL adjacency (src ids)
__device__ float g_dinv[NN];
__device__ int   g_is64;
__device__ __align__(16) float g_buf0[ROWS * HH];
__device__ __align__(16) float g_buf1[ROWS * HH];
__device__ float g_bnsum1[HH], g_bnsq1[HH];   // layer-1 BN stats
__device__ float g_bnsum2[HH], g_bnsq2[HH];   // layer-2 BN stats
// W fragment packs (bf16 hi/lo, m16n8k16): 8 k-chunks x 1024 u32 (16nt x 32 x 2)
__device__ __align__(16) unsigned g_fW1hi[8192];
__device__ __align__(16) unsigned g_fW1lo[8192];
__device__ __align__(16) unsigned g_fW2hi[8192];
__device__ __align__(16) unsigned g_fW2lo[8192];
// Wc fragments: 8 k-chunks x 2 nt x 32 lanes x 2 regs = 1024 u32
__device__ __align__(16) unsigned g_fWchi[1024];
__device__ __align__(16) unsigned g_fWclo[1024];

// ---------------- helpers ----------------------------------------------------
__device__ __forceinline__ unsigned short bfbits(float x) {
    __nv_bfloat16 h = __float2bfloat16_rn(x);
    return *(unsigned short*)&h;
}
__device__ __forceinline__ float bffloat(unsigned short u) {
    __nv_bfloat16 h = *(__nv_bfloat16*)&u;
    return __bfloat162float(h);
}
// split (x,y) into packed bf16x2 hi and lo parts (lower 16 bits = x)
__device__ __forceinline__ void bfsplit2(float x, float y, unsigned& hi, unsigned& lo) {
    unsigned short hx = bfbits(x), hy = bfbits(y);
    unsigned short lx = bfbits(x - bffloat(hx));
    unsigned short ly = bfbits(y - bffloat(hy));
    hi = (unsigned)hx | ((unsigned)hy << 16);
    lo = (unsigned)lx | ((unsigned)ly << 16);
}

__device__ __forceinline__ void mma_bf16(float* d, unsigned a0, unsigned a1,
                                         unsigned a2, unsigned a3,
                                         unsigned b0, unsigned b1) {
    asm volatile(
        "mma.sync.aligned.m16n8k16.row.col.f32.bf16.bf16.f32 "
        "{%0,%1,%2,%3},{%4,%5,%6,%7},{%8,%9},{%0,%1,%2,%3};\n"
        : "+f"(d[0]), "+f"(d[1]), "+f"(d[2]), "+f"(d[3])
        : "r"(a0), "r"(a1), "r"(a2), "r"(a3), "r"(b0), "r"(b1));
}

__device__ __forceinline__ int edge_at2(const void* eiv, int is64, long idx) {
    return is64 ? (int)((const long long*)eiv)[idx] : ((const int*)eiv)[idx];
}

// compute BN affine coeffs for channel c from raw stats
__device__ __forceinline__ void bn_coeff(const float* bnsum, const float* bnsq,
                                         const float* gamma, const float* beta,
                                         int c, float& sc, float& sh) {
    float cnt = (float)ROWS;
    float mean = bnsum[c] / cnt;
    float var = bnsq[c] / cnt - mean * mean;
    float inv = rsqrtf(var + 1e-5f);
    sc = gamma[c] * inv;
    sh = beta[c] - mean * sc;
}

// ---------------- graph prep -------------------------------------------------
__global__ void k_zero(const int* __restrict__ ei32) {
    int i = blockIdx.x * blockDim.x + threadIdx.x;
    if (i < NN) g_fill[i] = 0;
    if (i < HH) {
        g_bnsum1[i] = 0.f; g_bnsq1[i] = 0.f;
        g_bnsum2[i] = 0.f; g_bnsq2[i] = 0.f;
    }
    if (blockIdx.x == 0 && threadIdx.x < 32) {
        int lane = threadIdx.x;
        int nz = (ei32[2 * lane + 1] != 0) | (ei32[2 * (lane + 32) + 1] != 0);
        unsigned m = __ballot_sync(0xffffffffu, nz);
        if (lane == 0) g_is64 = (m == 0);
    }
}

__global__ void k_fill_ell(const void* __restrict__ eiv) {
    int is64 = g_is64;
    long e0 = (long)(blockIdx.x * blockDim.x + threadIdx.x) * 4;   // grid covers EE exactly
    int s[4], d[4];
#pragma unroll
    for (int i = 0; i < 4; i++) {
        s[i] = edge_at2(eiv, is64, e0 + i);
        d[i] = edge_at2(eiv, is64, (long)EE + e0 + i);
    }
#pragma unroll
    for (int i = 0; i < 4; i++) {
        int p = atomicAdd(&g_fill[d[i]], 1);
        g_ell[d[i] * PAD + p] = s[i];
    }
}

__global__ void k_dinv() {
    int i = blockIdx.x * blockDim.x + threadIdx.x;
    if (i < NN) g_dinv[i] = rsqrtf((float)(g_fill[i] + 1));   // +1 = self loop
}

// ---------------- W pack (bf16 m16n8k16 fragments, fork stream) ---------------
// B frag: within k-chunk of 16: kk -> reg r=kk>>3, t=(kk&7)>>1, half=kk&1;
// lane = (n&7)*4 + t. b0 = B[2t..2t+1][g], b1 = B[2t+8..2t+9][g].
__global__ void k_prepw(const float* __restrict__ W1, const float* __restrict__ W2,
                        const float* __restrict__ Wc) {
    int blk = blockIdx.x;                 // 0-7 W1, 8-15 W2, 16 Wc
    if (blk < 16) {
        int n = threadIdx.x;
        const float* W = (blk < 8) ? W1 : W2;
        unsigned* fh = (blk < 8) ? g_fW1hi : g_fW2hi;
        unsigned* fl = (blk < 8) ? g_fW1lo : g_fW2lo;
        int kt = blk & 7;
        int nt = n >> 3;
        for (int kk = 0; kk < 16; kk++) {
            int k = kt * 16 + kk;
            float w = W[k * HH + n];
            unsigned short hb = bfbits(w);
            unsigned short lb = bfbits(w - bffloat(hb));
            int r = kk >> 3, t = (kk & 7) >> 1, half = kk & 1;
            int lane = ((n & 7) << 2) | t;
            int idx = ((kt * 16 + nt) * 32 + lane) * 2 + r;
            ((unsigned short*)fh)[idx * 2 + half] = hb;
            ((unsigned short*)fl)[idx * 2 + half] = lb;
        }
    } else {
        int n = threadIdx.x & 15;
        int kt = threadIdx.x >> 4;        // 0..7
        int nt = n >> 3;
        for (int kk = 0; kk < 16; kk++) {
            int k = kt * 16 + kk;
            float w = (n < OO) ? Wc[k * OO + n] : 0.f;
            unsigned short hb = bfbits(w);
            unsigned short lb = bfbits(w - bffloat(hb));
            int r = kk >> 3, t = (kk & 7) >> 1, half = kk & 1;
            int lane = ((n & 7) << 2) | t;
            int idx = ((kt * 2 + nt) * 32 + lane) * 2 + r;
            ((unsigned short*)g_fWchi)[idx * 2 + half] = hb;
            ((unsigned short*)g_fWclo)[idx * 2 + half] = lb;
        }
    }
}

// ---------------- tensor-core GEMM (bf16x3): C = affine(A) @ Wfrag -----------
// smem double-buffered B, 256 threads, 2D grid (x: row tiles, y: batch).
// ALAYOUT 0: A row = b*NN+n (external x); 1: row = n*2+b (g_buf1)
template <int ALAYOUT, int WSEL, bool AFFINE>
__global__ void __launch_bounds__(256) k_gemm_tc(const float* __restrict__ Ain,
                                                 const float* __restrict__ gamma,
                                                 const float* __restrict__ beta) {
    __shared__ __align__(16) unsigned sHi[2][1024];
    __shared__ __align__(16) unsigned sLo[2][1024];
    __shared__ float sSc[HH], sSh[HH];
    const float* A = ALAYOUT ? (const float*)g_buf1 : Ain;
    const unsigned* fH = WSEL ? g_fW2hi : g_fW1hi;
    const unsigned* fL = WSEL ? g_fW2lo : g_fW1lo;

    int tid = threadIdx.x, lane = tid & 31, warp = tid >> 5;
    int b = blockIdx.y;
    int rowBase = blockIdx.x * 128;
    int g = lane >> 2, t = lane & 3;
    int r0 = rowBase + warp * 16 + g;
    int r1 = r0 + 8;
    int rc0 = r0 < NN ? r0 : NN - 1;
    int rc1 = r1 < NN ? r1 : NN - 1;
    long a0b = ALAYOUT ? ((long)rc0 * 2 + b) * HH : ((long)b * NN + rc0) * HH;
    long a1b = ALAYOUT ? ((long)rc1 * 2 + b) * HH : ((long)b * NN + rc1) * HH;

    if (AFFINE && tid < HH) {
        float sc, sh;
        bn_coeff(g_bnsum1, g_bnsq1, gamma, beta, tid, sc, sh);
        sSc[tid] = sc;
        sSh[tid] = sh;
    }

    float acc[16][4];
#pragma unroll
    for (int i = 0; i < 16; i++)
#pragma unroll
        for (int j = 0; j < 4; j++) acc[i][j] = 0.f;

    int ld = tid * 4;
    *(uint4*)&sHi[0][ld] = *(const uint4*)&fH[ld];
    *(uint4*)&sLo[0][ld] = *(const uint4*)&fL[ld];

    // A prefetch for chunk 0: rows r0/r1, cols 2t..2t+1 and 2t+8..2t+9
    float2 pa = __ldg((const float2*)(A + a0b + 2 * t));
    float2 pb = __ldg((const float2*)(A + a1b + 2 * t));
    float2 pc = __ldg((const float2*)(A + a0b + 2 * t + 8));
    float2 pd = __ldg((const float2*)(A + a1b + 2 * t + 8));
    __syncthreads();

    for (int c = 0; c < 8; c++) {
        int cur = c & 1;
        uint4 nh, nl;
        float2 na, nb, nc2, nd;
        if (c < 7) {
            int k1 = (c + 1) * 16;
            na  = __ldg((const float2*)(A + a0b + k1 + 2 * t));
            nb  = __ldg((const float2*)(A + a1b + k1 + 2 * t));
            nc2 = __ldg((const float2*)(A + a0b + k1 + 2 * t + 8));
            nd  = __ldg((const float2*)(A + a1b + k1 + 2 * t + 8));
            nh = *(const uint4*)&fH[(c + 1) * 1024 + ld];
            nl = *(const uint4*)&fL[(c + 1) * 1024 + ld];
        }
        int k0 = c * 16;
        if (AFFINE) {
            float sA = sSc[k0 + 2 * t],     hA = sSh[k0 + 2 * t];
            float sB = sSc[k0 + 2 * t + 1], hB = sSh[k0 + 2 * t + 1];
            float sC = sSc[k0 + 2 * t + 8], hC = sSh[k0 + 2 * t + 8];
            float sD = sSc[k0 + 2 * t + 9], hD = sSh[k0 + 2 * t + 9];
            pa.x = pa.x * sA + hA;  pa.y = pa.y * sB + hB;
            pb.x = pb.x * sA + hA;  pb.y = pb.y * sB + hB;
            pc.x = pc.x * sC + hC;  pc.y = pc.y * sD + hD;
            pd.x = pd.x * sC + hC;  pd.y = pd.y * sD + hD;
        }
        // A frags: a0=(g, 2t..2t+1) a1=(g+8, 2t..) a2=(g, 2t+8..) a3=(g+8, 2t+8..)
        unsigned ah0, al0, ah1, al1, ah2, al2, ah3, al3;
        bfsplit2(pa.x, pa.y, ah0, al0);
        bfsplit2(pb.x, pb.y, ah1, al1);
        bfsplit2(pc.x, pc.y, ah2, al2);
        bfsplit2(pd.x, pd.y, ah3, al3);

#pragma unroll
        for (int nt = 0; nt < 16; nt++) {
            int off = nt * 64 + lane * 2;
            unsigned bh0 = sHi[cur][off], bh1 = sHi[cur][off + 1];
            unsigned bl0 = sLo[cur][off], bl1 = sLo[cur][off + 1];
            mma_bf16(acc[nt], ah0, ah1, ah2, ah3, bh0, bh1);
            mma_bf16(acc[nt], al0, al1, al2, al3, bh0, bh1);
            mma_bf16(acc[nt], ah0, ah1, ah2, ah3, bl0, bl1);
        }
        __syncthreads();
        if (c < 7) {
            int nxt = cur ^ 1;
            *(uint4*)&sHi[nxt][ld] = nh;
            *(uint4*)&sLo[nxt][ld] = nl;
            pa = na; pb = nb; pc = nc2; pd = nd;
        }
        __syncthreads();
    }

#pragma unroll
    for (int nt = 0; nt < 16; nt++) {
        int col = nt * 8 + 2 * t;
        if (r0 < NN)
            *(float2*)&g_buf0[((long)r0 * 2 + b) * HH + col] =
                make_float2(acc[nt][0], acc[nt][1]);
        if (r1 < NN)
            *(float2*)&g_buf0[((long)r1 * 2 + b) * HH + col] =
                make_float2(acc[nt][2], acc[nt][3]);
    }
}

// ---------------- aggregation + fused BN stats (per-layer buffers) -----------
template <int LAYER>
__global__ void __launch_bounds__(256) k_aggbn(const float* __restrict__ bias) {
    float* bnsum = (LAYER == 1) ? g_bnsum1 : g_bnsum2;
    float* bnsq  = (LAYER == 1) ? g_bnsq1 : g_bnsq2;
    __shared__ float ssum[HH], ssq[HH];
    int tid = threadIdx.x;
    if (tid < HH) { ssum[tid] = 0.f; ssq[tid] = 0.f; }
    __syncthreads();

    int node = (blockIdx.x * blockDim.x + tid) >> 5;   // grid*8 == NN exactly
    int lane = tid & 31;
    float din = g_dinv[node];

    const float4* h4 = (const float4*)g_buf0;
    long base = (long)node * 64;
    float4 v0 = __ldg(&h4[base + lane]);
    float4 v1 = __ldg(&h4[base + 32 + lane]);
    float4 a0, a1;
    a0.x = din * v0.x; a0.y = din * v0.y; a0.z = din * v0.z; a0.w = din * v0.w;
    a1.x = din * v1.x; a1.y = din * v1.y; a1.z = din * v1.z; a1.w = din * v1.w;

    int cnt = g_fill[node];
    const int* row = g_ell + node * PAD;

#define AGG_EDGE(S)                                                        \
    {                                                                      \
        int _s = (S);                                                      \
        float w = __ldg(&g_dinv[_s]);                                      \
        long sb = (long)_s * 64;                                           \
        float4 u0 = __ldg(&h4[sb + lane]);                                 \
        float4 u1 = __ldg(&h4[sb + 32 + lane]);                            \
        a0.x += w * u0.x; a0.y += w * u0.y;                                \
        a0.z += w * u0.z; a0.w += w * u0.w;                                \
        a1.x += w * u1.x; a1.y += w * u1.y;                                \
        a1.z += w * u1.z; a1.w += w * u1.w;                                \
    }

    int i = 0;
    for (; i + 4 <= cnt; i += 4) {
        int4 ss = __ldg((const int4*)(row + i));    // broadcast, 1 LDG / 4 edges
        AGG_EDGE(ss.x); AGG_EDGE(ss.y); AGG_EDGE(ss.z); AGG_EDGE(ss.w);
    }
    for (; i < cnt; ++i) AGG_EDGE(row[i]);
#undef AGG_EDGE

    float4 bv = *(const float4*)(bias + lane * 4);
    float4 rr0, rr1;
    rr0.x = fmaxf(din * a0.x + bv.x, 0.f);
    rr0.y = fmaxf(din * a0.y + bv.y, 0.f);
    rr0.z = fmaxf(din * a0.z + bv.z, 0.f);
    rr0.w = fmaxf(din * a0.w + bv.w, 0.f);
    rr1.x = fmaxf(din * a1.x + bv.x, 0.f);
    rr1.y = fmaxf(din * a1.y + bv.y, 0.f);
    rr1.z = fmaxf(din * a1.z + bv.z, 0.f);
    rr1.w = fmaxf(din * a1.w + bv.w, 0.f);

    float4* o4 = (float4*)g_buf1;
    o4[base + lane] = rr0;
    o4[base + 32 + lane] = rr1;

    int ch = lane * 4;
    atomicAdd(&ssum[ch + 0], rr0.x + rr1.x);
    atomicAdd(&ssum[ch + 1], rr0.y + rr1.y);
    atomicAdd(&ssum[ch + 2], rr0.z + rr1.z);
    atomicAdd(&ssum[ch + 3], rr0.w + rr1.w);
    atomicAdd(&ssq[ch + 0], rr0.x * rr0.x + rr1.x * rr1.x);
    atomicAdd(&ssq[ch + 1], rr0.y * rr0.y + rr1.y * rr1.y);
    atomicAdd(&ssq[ch + 2], rr0.z * rr0.z + rr1.z * rr1.z);
    atomicAdd(&ssq[ch + 3], rr0.w * rr0.w + rr1.w * rr1.w);
    __syncthreads();
    if (tid < HH) {
        atomicAdd(&bnsum[tid], ssum[tid]);
        atomicAdd(&bnsq[tid], ssq[tid]);
    }
}

// ---------------- tensor-core classifier (bf16x3) ----------------------------
__global__ void __launch_bounds__(256) k_cls_tc(const float* __restrict__ bc,
                                                const float* __restrict__ gamma,
                                                const float* __restrict__ beta,
                                                float* __restrict__ out) {
    __shared__ __align__(16) unsigned sWh[1024], sWl[1024];
    __shared__ float sSc[HH], sSh[HH];
    __shared__ float sbc[16];
    int tid = threadIdx.x, lane = tid & 31, warp = tid >> 5;

    // stage all Wc fragments (8KB) once
    int ld = tid * 4;
    *(uint4*)&sWh[ld] = *(const uint4*)&g_fWchi[ld];
    *(uint4*)&sWl[ld] = *(const uint4*)&g_fWclo[ld];
    if (tid < HH) {
        float sc, sh;
        bn_coeff(g_bnsum2, g_bnsq2, gamma, beta, tid, sc, sh);
        sSc[tid] = sc;
        sSh[tid] = sh;
    }
    if (tid < 16) sbc[tid] = (tid < OO) ? bc[tid] : 0.f;

    int g = lane >> 2, t = lane & 3;
    int r0 = blockIdx.x * 128 + warp * 16 + g;
    int r1 = r0 + 8;
    int rc0 = r0 < ROWS ? r0 : ROWS - 1;
    int rc1 = r1 < ROWS ? r1 : ROWS - 1;
    const float* A = (const float*)g_buf1;
    long a0b = (long)rc0 * HH;
    long a1b = (long)rc1 * HH;

    float acc[2][4];
#pragma unroll
    for (int i = 0; i < 2; i++)
#pragma unroll
        for (int j = 0; j < 4; j++) acc[i][j] = 0.f;

    float2 pa = __ldg((const float2*)(A + a0b + 2 * t));
    float2 pb = __ldg((const float2*)(A + a1b + 2 * t));
    float2 pc = __ldg((const float2*)(A + a0b + 2 * t + 8));
    float2 pd = __ldg((const float2*)(A + a1b + 2 * t + 8));
    __syncthreads();

    for (int c = 0; c < 8; c++) {
        float2 na, nb, nc2, nd;
        if (c < 7) {
            int k1 = (c + 1) * 16;
            na  = __ldg((const float2*)(A + a0b + k1 + 2 * t));
            nb  = __ldg((const float2*)(A + a1b + k1 + 2 * t));
            nc2 = __ldg((const float2*)(A + a0b + k1 + 2 * t + 8));
            nd  = __ldg((const float2*)(A + a1b + k1 + 2 * t + 8));
        }
        int k0 = c * 16;
        float sA = sSc[k0 + 2 * t],     hA = sSh[k0 + 2 * t];
        float sB = sSc[k0 + 2 * t + 1], hB = sSh[k0 + 2 * t + 1];
        float sC = sSc[k0 + 2 * t + 8], hC = sSh[k0 + 2 * t + 8];
        float sD = sSc[k0 + 2 * t + 9], hD = sSh[k0 + 2 * t + 9];
        pa.x = pa.x * sA + hA;  pa.y = pa.y * sB + hB;
        pb.x = pb.x * sA + hA;  pb.y = pb.y * sB + hB;
        pc.x = pc.x * sC + hC;  pc.y = pc.y * sD + hD;
        pd.x = pd.x * sC + hC;  pd.y = pd.y * sD + hD;

        unsigned ah0, al0, ah1, al1, ah2, al2, ah3, al3;
        bfsplit2(pa.x, pa.y, ah0, al0);
        bfsplit2(pb.x, pb.y, ah1, al1);
        bfsplit2(pc.x, pc.y, ah2, al2);
        bfsplit2(pd.x, pd.y, ah3, al3);

#pragma unroll
        for (int nt = 0; nt < 2; nt++) {
            int off = c * 128 + nt * 64 + lane * 2;
            unsigned bh0 = sWh[off], bh1 = sWh[off + 1];
            unsigned bl0 = sWl[off], bl1 = sWl[off + 1];
            mma_bf16(acc[nt], ah0, ah1, ah2, ah3, bh0, bh1);
            mma_bf16(acc[nt], al0, al1, al2, al3, bh0, bh1);
            mma_bf16(acc[nt], ah0, ah1, ah2, ah3, bl0, bl1);
        }
        if (c < 7) { pa = na; pb = nb; pc = nc2; pd = nd; }
    }

    // epilogue: out[(b*NN+n)*OO + col], r = n*2+b
#pragma unroll
    for (int nt = 0; nt < 2; nt++) {
        int col = nt * 8 + 2 * t;
        if (col + 1 < OO) {
            if (r0 < ROWS) {
                long o = ((long)(r0 & 1) * NN + (r0 >> 1)) * OO + col;
                out[o]     = acc[nt][0] + sbc[col];
                out[o + 1] = acc[nt][1] + sbc[col + 1];
            }
            if (r1 < ROWS) {
                long o = ((long)(r1 & 1) * NN + (r1 >> 1)) * OO + col;
                out[o]     = acc[nt][2] + sbc[col];
                out[o + 1] = acc[nt][3] + sbc[col + 1];
            }
        }
    }
}

// ---------------- launch -----------------------------------------------------
extern "C" void kernel_launch(void* const* d_in, const int* in_sizes, int n_in,
                              void* d_out, int out_size) {
    const float* x  = (const float*)d_in[0];
    const float* W1 = (const float*)d_in[1];
    const float* b1 = (const float*)d_in[2];
    const float* W2 = (const float*)d_in[3];
    const float* b2 = (const float*)d_in[4];
    const float* g1 = (const float*)d_in[5];
    const float* bt1 = (const float*)d_in[6];
    const float* g2 = (const float*)d_in[7];
    const float* bt2 = (const float*)d_in[8];
    const float* Wc = (const float*)d_in[9];
    const float* bc = (const float*)d_in[10];
    const void* ei = d_in[11];
    float* out = (float*)d_out;

    dim3 ggrid((NN + 127) / 128, BBATCH);   // 157 x 2, 256 threads

    // Fork: W pack + layer-1 GEMM concurrent with graph build.
    cudaStream_t s1;
    cudaStreamCreateWithFlags(&s1, cudaStreamNonBlocking);
    cudaEvent_t ev0, ev1;
    cudaEventCreateWithFlags(&ev0, cudaEventDisableTiming);
    cudaEventCreateWithFlags(&ev1, cudaEventDisableTiming);

    cudaEventRecord(ev0, 0);
    cudaStreamWaitEvent(s1, ev0, 0);
    k_prepw<<<17, 128, 0, s1>>>(W1, W2, Wc);
    k_gemm_tc<0, 0, false><<<ggrid, 256, 0, s1>>>(x, nullptr, nullptr);
    cudaEventRecord(ev1, s1);

    // main stream: graph build (+ BN stat buffer zeroing)
    k_zero<<<(NN + 255) / 256, 256>>>((const int*)ei);
    k_fill_ell<<<EE / 1024, 256>>>(ei);
    k_dinv<<<(NN + 255) / 256, 256>>>();

    // join
    cudaStreamWaitEvent(0, ev1, 0);

    // layer 1 tail (stats -> g_bnsum1/g_bnsq1)
    k_aggbn<1><<<NN / 8, 256>>>(b1);

    // layer 2 (BN1 affine computed per-block from raw stats)
    k_gemm_tc<1, 1, true><<<ggrid, 256>>>(nullptr, g1, bt1);
    k_aggbn<2><<<NN / 8, 256>>>(b2);

    // classifier: tensor-core GEMM, BN2 affine on A-path
    k_cls_tc<<<(ROWS + 127) / 128, 256>>>(bc, g2, bt2, out);
}